// round 7
// baseline (speedup 1.0000x reference)
#include <cuda_runtime.h>
#include <cstdint>

// preds/target = [B=8, C=21, H=512, W=512] fp32, contiguous.
// R7 = R4's full occupancy (8 blocks/SM, 32-reg loop) + R5's exact balance:
// 1184 blocks, each owns a contiguous ~9299-float4 range (+-1 balanced).
// A range crosses at most ONE slab boundary (slab = 65536 float4), so <=2
// uniform-class sub-ranges per block. MLP from 64 resident warps/SM.
// Fused: count -> last-block finalize -> self-reset (graph-replay safe).

#define NCLS 21
#define SLAB_V4 65536ULL                     // 512*512/4 float4 per (b,c) slab
#define TOTAL_V4 (168ULL * SLAB_V4)          // 11,010,048
#define THREADS 256
#define GRID_BLOCKS 1184                     // 148 SMs * 8 blocks (one wave)

__device__ int g_inter[NCLS];
__device__ int g_pred[NCLS];
__device__ int g_targ[NCLS];
__device__ unsigned int g_done;              // zero-init; reset by last block

struct Acc { int inter, ps, ts; };

__device__ __forceinline__ void acc4(Acc& a, float4 p, float4 t) {
    int p0 = p.x >= 0.5f, p1 = p.y >= 0.5f, p2 = p.z >= 0.5f, p3 = p.w >= 0.5f;
    int t0 = t.x == 1.0f, t1 = t.y == 1.0f, t2 = t.z == 1.0f, t3 = t.w == 1.0f;
    a.ps    += p0 + p1 + p2 + p3;
    a.ts    += t0 + t1 + t2 + t3;
    a.inter += (p0 & t0) + (p1 & t1) + (p2 & t2) + (p3 & t3);
}

__device__ __forceinline__ Acc accum_range(
    const float4* __restrict__ p4, const float4* __restrict__ t4,
    size_t lo, size_t hi)
{
    Acc a = {0, 0, 0};
    #pragma unroll 4
    for (size_t i = lo + threadIdx.x; i < hi; i += THREADS) {
        float4 p = __ldcs(p4 + i);
        float4 t = __ldcs(t4 + i);
        acc4(a, p, t);
    }
    return a;
}

__device__ __forceinline__ void block_commit(Acc a, int cls, int* s_cnt) {
    #pragma unroll
    for (int o = 16; o > 0; o >>= 1) {
        a.inter += __shfl_down_sync(0xffffffffu, a.inter, o);
        a.ps    += __shfl_down_sync(0xffffffffu, a.ps, o);
        a.ts    += __shfl_down_sync(0xffffffffu, a.ts, o);
    }
    if (threadIdx.x < 3) s_cnt[threadIdx.x] = 0;
    __syncthreads();
    if ((threadIdx.x & 31) == 0) {
        atomicAdd(&s_cnt[0], a.inter);
        atomicAdd(&s_cnt[1], a.ps);
        atomicAdd(&s_cnt[2], a.ts);
    }
    __syncthreads();
    if (threadIdx.x == 0) {
        atomicAdd(&g_inter[cls], s_cnt[0]);
        atomicAdd(&g_pred[cls],  s_cnt[1]);
        atomicAdd(&g_targ[cls],  s_cnt[2]);
    }
    __syncthreads();   // protect s_cnt reuse
}

__global__ __launch_bounds__(THREADS, 8) void jidx_fused_kernel(
    const float4* __restrict__ preds4,
    const float4* __restrict__ targ4,
    float* __restrict__ out)
{
    __shared__ int s_cnt[3];
    __shared__ int s_last;

    const size_t start = (size_t)blockIdx.x       * TOTAL_V4 / GRID_BLOCKS;
    const size_t end   = (size_t)(blockIdx.x + 1) * TOTAL_V4 / GRID_BLOCKS;

    // First slab boundary strictly after start.
    const size_t b1  = (start / SLAB_V4 + 1) * SLAB_V4;
    const size_t mid = (b1 < end) ? b1 : end;

    {
        const int cls = (int)((start / SLAB_V4) % NCLS);
        Acc a = accum_range(preds4, targ4, start, mid);
        block_commit(a, cls, s_cnt);
    }
    if (mid < end) {
        const int cls = (int)((mid / SLAB_V4) % NCLS);
        Acc a = accum_range(preds4, targ4, mid, end);
        block_commit(a, cls, s_cnt);
    }

    // Completion protocol: one arrival per block.
    if (threadIdx.x == 0) {
        __threadfence();                 // publish counts before done++
        unsigned int t = atomicAdd(&g_done, 1u);
        s_last = (t == (unsigned int)(GRID_BLOCKS - 1));
    }
    __syncthreads();

    if (s_last) {
        __threadfence();                 // acquire all published counts
        if (threadIdx.x < NCLS) {
            int i = threadIdx.x;
            float fi  = (float)g_inter[i];
            float uni = (float)(g_pred[i] + g_targ[i] - g_inter[i]);
            out[i] = (uni == 0.0f) ? __int_as_float(0x7fc00000)  // NaN
                                   : fi / fmaxf(uni, 1.0f);
            // self-reset for next graph replay
            g_inter[i] = 0;
            g_pred[i]  = 0;
            g_targ[i]  = 0;
        }
        if (threadIdx.x == 0) g_done = 0u;
    }
}

extern "C" void kernel_launch(void* const* d_in, const int* in_sizes, int n_in,
                              void* d_out, int out_size) {
    const float4* preds4 = (const float4*)d_in[0];
    const float4* targ4  = (const float4*)d_in[1];
    float* out = (float*)d_out;

    jidx_fused_kernel<<<GRID_BLOCKS, THREADS>>>(preds4, targ4, out);
}

// round 8
// speedup vs baseline: 1.0826x; 1.0826x over previous
#include <cuda_runtime.h>
#include <cstdint>

// preds/target = [B=8, C=21, H=512, W=512] fp32, contiguous.
// R8: R4's unit-interleaved access (best measured DRAM%) + dynamic
// work-stealing over fine units to remove end-of-kernel quantization.
// Unit = 1024 float4 (64 per slab -> class uniform per unit), 10752 units.
// Blocks pull units via a global counter; commit to global atomics only on
// class change. Fused last-block finalize + full self-reset (replay safe).

#define NCLS 21
#define UNITS_PER_SLAB 64
#define UNIT_V4 1024                          // 65536 / 64
#define TOTAL_UNITS (168 * UNITS_PER_SLAB)    // 10752
#define THREADS 256
#define ITERS (UNIT_V4 / THREADS)             // 4
#define GRID_BLOCKS 1184                      // 148 SMs * 8 blocks (one wave)

__device__ int g_inter[NCLS];
__device__ int g_pred[NCLS];
__device__ int g_targ[NCLS];
__device__ unsigned int g_next;               // work-stealing cursor
__device__ unsigned int g_done;               // completion count

struct Acc { int inter, ps, ts; };

__device__ __forceinline__ void acc4(Acc& a, float4 p, float4 t) {
    int p0 = p.x >= 0.5f, p1 = p.y >= 0.5f, p2 = p.z >= 0.5f, p3 = p.w >= 0.5f;
    int t0 = t.x == 1.0f, t1 = t.y == 1.0f, t2 = t.z == 1.0f, t3 = t.w == 1.0f;
    a.ps    += p0 + p1 + p2 + p3;
    a.ts    += t0 + t1 + t2 + t3;
    a.inter += (p0 & t0) + (p1 & t1) + (p2 & t2) + (p3 & t3);
}

__device__ __forceinline__ void block_commit(Acc a, int cls, int* s_cnt) {
    #pragma unroll
    for (int o = 16; o > 0; o >>= 1) {
        a.inter += __shfl_down_sync(0xffffffffu, a.inter, o);
        a.ps    += __shfl_down_sync(0xffffffffu, a.ps, o);
        a.ts    += __shfl_down_sync(0xffffffffu, a.ts, o);
    }
    if (threadIdx.x < 3) s_cnt[threadIdx.x] = 0;
    __syncthreads();
    if ((threadIdx.x & 31) == 0) {
        atomicAdd(&s_cnt[0], a.inter);
        atomicAdd(&s_cnt[1], a.ps);
        atomicAdd(&s_cnt[2], a.ts);
    }
    __syncthreads();
    if (threadIdx.x == 0) {
        atomicAdd(&g_inter[cls], s_cnt[0]);
        atomicAdd(&g_pred[cls],  s_cnt[1]);
        atomicAdd(&g_targ[cls],  s_cnt[2]);
    }
    __syncthreads();   // protect s_cnt reuse
}

__global__ __launch_bounds__(THREADS, 8) void jidx_fused_kernel(
    const float4* __restrict__ preds4,
    const float4* __restrict__ targ4,
    float* __restrict__ out)
{
    __shared__ int s_cnt[3];
    __shared__ int s_last;
    __shared__ unsigned int s_u;

    Acc a = {0, 0, 0};
    int cur = -1;

    for (;;) {
        __syncthreads();                         // prior s_u reads complete
        if (threadIdx.x == 0) s_u = atomicAdd(&g_next, 1u);
        __syncthreads();
        unsigned int u = s_u;
        if (u >= TOTAL_UNITS) break;             // uniform exit

        const int cls = (int)((u >> 6) % NCLS);  // slab = u / 64
        if (cls != cur) {
            if (cur >= 0) block_commit(a, cur, s_cnt);
            a.inter = 0; a.ps = 0; a.ts = 0;
            cur = cls;
        }

        const size_t base = (size_t)u * UNIT_V4 + threadIdx.x;
        #pragma unroll
        for (int j = 0; j < ITERS; ++j) {
            float4 p = __ldcs(preds4 + base + (size_t)j * THREADS);
            float4 t = __ldcs(targ4  + base + (size_t)j * THREADS);
            acc4(a, p, t);
        }
    }
    if (cur >= 0) block_commit(a, cur, s_cnt);

    // Completion protocol: one arrival per block.
    if (threadIdx.x == 0) {
        __threadfence();                 // publish counts before done++
        unsigned int t = atomicAdd(&g_done, 1u);
        s_last = (t == (unsigned int)(GRID_BLOCKS - 1));
    }
    __syncthreads();

    if (s_last) {
        __threadfence();                 // acquire all published counts
        if (threadIdx.x < NCLS) {
            int i = threadIdx.x;
            float fi  = (float)g_inter[i];
            float uni = (float)(g_pred[i] + g_targ[i] - g_inter[i]);
            out[i] = (uni == 0.0f) ? __int_as_float(0x7fc00000)  // NaN
                                   : fi / fmaxf(uni, 1.0f);
            // self-reset for next graph replay
            g_inter[i] = 0;
            g_pred[i]  = 0;
            g_targ[i]  = 0;
        }
        if (threadIdx.x == 0) { g_next = 0u; g_done = 0u; }
    }
}

extern "C" void kernel_launch(void* const* d_in, const int* in_sizes, int n_in,
                              void* d_out, int out_size) {
    const float4* preds4 = (const float4*)d_in[0];
    const float4* targ4  = (const float4*)d_in[1];
    float* out = (float*)d_out;

    jidx_fused_kernel<<<GRID_BLOCKS, THREADS>>>(preds4, targ4, out);
}